// round 15
// baseline (speedup 1.0000x reference)
#include <cuda_runtime.h>
#include <cuda_bf16.h>
#include <math.h>
#include <stdint.h>

#define N_NODES 25000
#define E_EDGES 250000
#define DD 128

// ---------------- scratch ----------------------------------------------------
__device__ float2 g_dn[(size_t)N_NODES * DD];        // (denom, numerator)
__device__ float  g_xw[(size_t)N_NODES * 256];       // [xW1 | xW2] per node
__device__ float  g_h1[(size_t)N_NODES * 2 * DD];    // after first MLP linear
__device__ float2 g_bnstat[2 * DD];                  // (sum, sumsq)
// interleaved bf16 weight images: u32 idx 2e = hi(e), 2e+1 = lo(e); rows [n][SP]
#define KP 72
#define SP (KP / 2)      // logical u32 row stride = 36 (conflict-free)
__device__ uint32_t g_We[6 * 128 * SP * 2];          // W_e^T, 6 images
__device__ uint32_t g_W1[4 * 128 * SP * 2];          // W_m1^T, 4 images
__device__ uint32_t g_W2[4 * 128 * SP * 2];          // W_m2^T, 4 images

// ---------------- prep: weights -> transposed split interleaved images -------
__global__ void prep_kernel(const float* __restrict__ W_e,
                            const float* __restrict__ W_m1,
                            const float* __restrict__ W_m2) {
    int i = blockIdx.x * 256 + threadIdx.x;
    float v; int idx; uint32_t* arr;
    if (i < 384 * 128) {
        int k = i >> 7, n = i & 127;
        v = W_e[i];
        idx = (((k >> 6) * 128) + n) * KP + (k & 63);
        arr = g_We;
    } else if (i < 384 * 128 + 128 * 256) {
        int j = i - 384 * 128;
        int k = j >> 8, n = j & 255;
        v = W_m1[j];
        int g = ((n >> 7) << 1) + (k >> 6);
        idx = (g * 128 + (n & 127)) * KP + (k & 63);
        arr = g_W1;
    } else if (i < 384 * 128 + 128 * 256 + 256 * 128) {
        int j = i - (384 * 128 + 128 * 256);
        int k = j >> 7, n = j & 127;
        v = W_m2[j];
        idx = (((k >> 6) * 128) + n) * KP + (k & 63);
        arr = g_W2;
    } else return;
    __nv_bfloat16 h = __float2bfloat16(v);
    __nv_bfloat16 l = __float2bfloat16(v - __bfloat162float(h));
    int e = idx >> 1, hh = idx & 1;
    unsigned short* p = (unsigned short*)arr;
    p[4 * e + hh]     = __bfloat16_as_ushort(h);
    p[4 * e + 2 + hh] = __bfloat16_as_ushort(l);
}

// ---------------- HMMA machinery ---------------------------------------------
__device__ __forceinline__ void mma_bf16(float* d, const uint32_t* a,
                                         uint32_t b0, uint32_t b1) {
    asm volatile(
        "mma.sync.aligned.m16n8k16.row.col.f32.bf16.bf16.f32 "
        "{%0,%1,%2,%3}, {%4,%5,%6,%7}, {%8,%9}, {%0,%1,%2,%3};"
        : "+f"(d[0]), "+f"(d[1]), "+f"(d[2]), "+f"(d[3])
        : "r"(a[0]), "r"(a[1]), "r"(a[2]), "r"(a[3]), "r"(b0), "r"(b1));
}

__device__ __forceinline__ void red_v4(float* gp, float a, float b, float c, float d) {
    asm volatile("red.global.add.v4.f32 [%0], {%1,%2,%3,%4};"
                 :: "l"(gp), "f"(a), "f"(b), "f"(c), "f"(d) : "memory");
}

__device__ __forceinline__ void split4(float4 v, uint32_t& h0, uint32_t& h1,
                                       uint32_t& l0, uint32_t& l1) {
    __nv_bfloat16 a0 = __float2bfloat16(v.x), a1 = __float2bfloat16(v.y);
    __nv_bfloat16 a2 = __float2bfloat16(v.z), a3 = __float2bfloat16(v.w);
    __nv_bfloat16 b0 = __float2bfloat16(v.x - __bfloat162float(a0));
    __nv_bfloat16 b1 = __float2bfloat16(v.y - __bfloat162float(a1));
    __nv_bfloat16 b2 = __float2bfloat16(v.z - __bfloat162float(a2));
    __nv_bfloat16 b3 = __float2bfloat16(v.w - __bfloat162float(a3));
    h0 = (uint32_t)__bfloat16_as_ushort(a0) | ((uint32_t)__bfloat16_as_ushort(a1) << 16);
    h1 = (uint32_t)__bfloat16_as_ushort(a2) | ((uint32_t)__bfloat16_as_ushort(a3) << 16);
    l0 = (uint32_t)__bfloat16_as_ushort(b0) | ((uint32_t)__bfloat16_as_ushort(b1) << 16);
    l1 = (uint32_t)__bfloat16_as_ushort(b2) | ((uint32_t)__bfloat16_as_ushort(b3) << 16);
}

// interleaved A store: one STS.128 writes (hi0, lo0, hi1, lo1)
__device__ __forceinline__ void store_a(uint32_t* AB, int ai,
                                        uint32_t h0, uint32_t h1,
                                        uint32_t l0, uint32_t l1) {
    *(uint4*)&AB[ai * 2] = make_uint4(h0, l0, h1, l1);
}

// fragment-reuse 3-term MMA on interleaved buffers: LDS.64 fetches hi+lo pairs
__device__ __forceinline__ void mma_chunk(const uint32_t* AB, const uint32_t* BB,
                                          float acc[2][8][4], int wm, int wn, int lane) {
#pragma unroll
    for (int ks = 0; ks < 4; ++ks) {
        const int kb = ks * 8;
        uint32_t ah[2][4], al[2][4];
#pragma unroll
        for (int mt = 0; mt < 2; ++mt) {
            int ar = wm * 32 + mt * 16 + (lane >> 2);
            int ac = kb + (lane & 3);
            uint2 p0 = *(const uint2*)&AB[(ar * SP + ac) * 2];
            uint2 p1 = *(const uint2*)&AB[((ar + 8) * SP + ac) * 2];
            uint2 p2 = *(const uint2*)&AB[(ar * SP + ac + 4) * 2];
            uint2 p3 = *(const uint2*)&AB[((ar + 8) * SP + ac + 4) * 2];
            ah[mt][0] = p0.x; ah[mt][1] = p1.x; ah[mt][2] = p2.x; ah[mt][3] = p3.x;
            al[mt][0] = p0.y; al[mt][1] = p1.y; al[mt][2] = p2.y; al[mt][3] = p3.y;
        }
#pragma unroll
        for (int nt = 0; nt < 8; ++nt) {
            int bo = (wn * 64 + nt * 8 + (lane >> 2)) * SP + kb + (lane & 3);
            uint2 bp0 = *(const uint2*)&BB[bo * 2];
            uint2 bp1 = *(const uint2*)&BB[(bo + 4) * 2];
            mma_bf16(acc[0][nt], ah[0], bp0.x, bp1.x);
            mma_bf16(acc[1][nt], ah[1], bp0.x, bp1.x);
            mma_bf16(acc[0][nt], ah[0], bp0.y, bp1.y);
            mma_bf16(acc[1][nt], ah[1], bp0.y, bp1.y);
            mma_bf16(acc[0][nt], al[0], bp0.x, bp1.x);
            mma_bf16(acc[1][nt], al[1], bp0.x, bp1.x);
        }
    }
}

// smem layout (bytes)
#define SM_IDX  0
#define SM_PAR  1024
#define SM_MUR  2560       // mu[128], rstd[128]
#define SM_AB   4096       // interleaved A: 36864 B
#define SM_BB   (SM_AB + 36864)   // interleaved B: 36864 B
#define SM_ES   SM_AB
#define ESW     132
#define ES4     33
#define SM_TOTAL_TC (SM_BB + 36864)           // 77824 -> 2 CTAs/SM
#define NB4     (128 * SP / 2)                // uint4 count per B image = 2304
// mlp2 params: low region (0..4096) + dead B-tail (71680..77824)
#define M2_SC   0
#define M2_SH   1024
#define M2_BM2  2048
#define M2_GN   2560
#define M2_BNN  3072
#define M2_SSC  3584
#define M2_CRW  71680
#define M2_MUW  72192
#define M2_RSW  72704

// ---------------- node precompute (folded init) ------------------------------
__global__ __launch_bounds__(256, 2)
void node_pre_kernel(const float* __restrict__ x)
{
    extern __shared__ __align__(128) char smem[];
    const int tid = threadIdx.x, wid = tid >> 5, lane = tid & 31;
    const int r0 = blockIdx.x * 128;
    const int by = blockIdx.y;
    const int wm = wid >> 1, wn = wid & 1;

    // folded init: zero g_dn + bnstat across all blocks
    {
        int nb = gridDim.x * 2;
        int bid = blockIdx.y * gridDim.x + blockIdx.x;
        size_t total = (size_t)N_NODES * DD;
        size_t per = (total + nb - 1) / nb;
        size_t s = (size_t)bid * per;
        size_t e = s + per; if (e > total) e = total;
        for (size_t i = s + tid; i < e; i += 256) g_dn[i] = make_float2(0.f, 0.f);
        if (bid == 0 && tid < 2 * DD) g_bnstat[tid] = make_float2(0.f, 0.f);
    }

    uint32_t* AB = (uint32_t*)(smem + SM_AB);
    uint32_t* BB = (uint32_t*)(smem + SM_BB);

    float acc[2][8][4];
#pragma unroll
    for (int mt = 0; mt < 2; ++mt)
#pragma unroll
        for (int nt = 0; nt < 8; ++nt)
#pragma unroll
            for (int q = 0; q < 4; ++q) acc[mt][nt][q] = 0.f;

    for (int c = 0; c < 2; ++c) {
        if (c) __syncthreads();
        {
            int row = tid >> 1, half = tid & 1;
            int r = min(r0 + row, N_NODES - 1);
            const float4* src = (const float4*)(x + (size_t)r * 128 + c * 64 + half * 32);
            int base = row * SP + half * 16;
#pragma unroll
            for (int i = 0; i < 8; ++i) {
                uint32_t h0, h1, l0, l1;
                split4(src[i], h0, h1, l0, l1);
                store_a(AB, base + i * 2, h0, h1, l0, l1);
            }
        }
        {
            const uint4* s = (const uint4*)(g_We + (size_t)(by * 2 + c) * (128 * SP * 2));
            uint4* d = (uint4*)BB;
#pragma unroll
            for (int j = tid; j < NB4; j += 256) d[j] = s[j];
        }
        __syncthreads();
        mma_chunk(AB, BB, acc, wm, wn, lane);
    }
#pragma unroll
    for (int mt = 0; mt < 2; ++mt) {
        int r = r0 + wm * 32 + mt * 16 + (lane >> 2);
#pragma unroll
        for (int nt = 0; nt < 8; ++nt) {
            int cc = by * 128 + wn * 64 + nt * 8 + ((lane & 3) << 1);
            if (r < N_NODES)
                *(float2*)&g_xw[(size_t)r * 256 + cc] = make_float2(acc[mt][nt][0], acc[mt][nt][1]);
            if (r + 8 < N_NODES)
                *(float2*)&g_xw[(size_t)(r + 8) * 256 + cc] = make_float2(acc[mt][nt][2], acc[mt][nt][3]);
        }
    }
}

// ---------------- edge kernel ------------------------------------------------
__global__ __launch_bounds__(256, 2)
void edge_mlp_tc(const float* __restrict__ x, const float* __restrict__ edge_attr,
                 const int* __restrict__ erow, const int* __restrict__ ecol,
                 const float* __restrict__ b_e, const float* __restrict__ g_e,
                 const float* __restrict__ be_e, const float* __restrict__ t_ptr,
                 float* __restrict__ e_out)
{
    extern __shared__ __align__(128) char smem[];
    const int tid = threadIdx.x, wid = tid >> 5, lane = tid & 31;
    const int e0 = blockIdx.x * 128;
    const int wm = wid >> 1, wn = wid & 1;

    int*   erow_s = (int*)(smem + SM_IDX);
    int*   ecol_s = erow_s + 128;
    float* par    = (float*)(smem + SM_PAR);
    float* mu_s   = (float*)(smem + SM_MUR);
    float* rs_s   = mu_s + 128;

    if (tid < 128) {
        int eid = min(e0 + tid, E_EDGES - 1);
        erow_s[tid] = erow[eid];
        ecol_s[tid] = ecol[eid];
        par[tid]       = b_e[tid];
        par[128 + tid] = g_e[tid];
        par[256 + tid] = be_e[tid];
    }
    __syncthreads();

    uint32_t* AB = (uint32_t*)(smem + SM_AB);
    uint32_t* BB = (uint32_t*)(smem + SM_BB);

    float acc[2][8][4];
#pragma unroll
    for (int mt = 0; mt < 2; ++mt)
#pragma unroll
        for (int nt = 0; nt < 8; ++nt)
#pragma unroll
            for (int q = 0; q < 4; ++q) acc[mt][nt][q] = 0.f;

    for (int c = 0; c < 2; ++c) {
        if (c) __syncthreads();
        {
            int row = tid >> 1, half = tid & 1;
            const float4* src = (const float4*)(edge_attr +
                (size_t)min(e0 + row, E_EDGES - 1) * 128 + c * 64 + half * 32);
            int base = row * SP + half * 16;
#pragma unroll
            for (int i = 0; i < 8; ++i) {
                uint32_t h0, h1, l0, l1;
                split4(src[i], h0, h1, l0, l1);
                store_a(AB, base + i * 2, h0, h1, l0, l1);
            }
        }
        {
            const uint4* s = (const uint4*)(g_We + (size_t)(4 + c) * (128 * SP * 2));
            uint4* d = (uint4*)BB;
#pragma unroll
            for (int j = tid; j < NB4; j += 256) d[j] = s[j];
        }
        __syncthreads();
        mma_chunk(AB, BB, acc, wm, wn, lane);
    }
    __syncthreads();          // smem -> Es reuse

    float* Es = (float*)(smem + SM_ES);
#pragma unroll
    for (int mt = 0; mt < 2; ++mt) {
        int r = wm * 32 + mt * 16 + (lane >> 2);
#pragma unroll
        for (int nt = 0; nt < 8; ++nt) {
            int cc = wn * 64 + nt * 8 + ((lane & 3) << 1);
            Es[r * ESW + cc]           = acc[mt][nt][0];
            Es[r * ESW + cc + 1]       = acc[mt][nt][1];
            Es[(r + 8) * ESW + cc]     = acc[mt][nt][2];
            Es[(r + 8) * ESW + cc + 1] = acc[mt][nt][3];
        }
    }
    __syncthreads();

    // Phase A: add node precomputes + bias, ReLU, LN stats (2 threads/edge)
    {
        int el = tid >> 1, h = tid & 1;
        float4* Es4 = (float4*)Es;
        const float4* par4 = (const float4*)par;
        const float4* xr4 = (const float4*)(g_xw + (size_t)erow_s[el] * 256);
        const float4* xc4 = (const float4*)(g_xw + (size_t)ecol_s[el] * 256 + 128);
        float s = 0.f, ss = 0.f;
#pragma unroll
        for (int i = 0; i < 16; ++i) {
            int q = i * 2 + h;
            float4 es = Es4[el * ES4 + q];
            float4 bb = par4[q];
            float4 xr = xr4[q];
            float4 xc = xc4[q];
            float4 v;
            v.x = fmaxf(es.x + bb.x + xr.x + xc.x, 0.f);
            v.y = fmaxf(es.y + bb.y + xr.y + xc.y, 0.f);
            v.z = fmaxf(es.z + bb.z + xr.z + xc.z, 0.f);
            v.w = fmaxf(es.w + bb.w + xr.w + xc.w, 0.f);
            Es4[el * ES4 + q] = v;
            s += v.x + v.y + v.z + v.w;
            ss += v.x * v.x + v.y * v.y + v.z * v.z + v.w * v.w;
        }
        s  += __shfl_xor_sync(0xffffffffu, s, 1);
        ss += __shfl_xor_sync(0xffffffffu, ss, 1);
        float mu = s * (1.f / 128.f);
        mu_s[el] = mu;
        rs_s[el] = rsqrtf(ss * (1.f / 128.f) - mu * mu + 1e-5f);
    }
    __syncthreads();

    // Phase B: normalize + residual -> e_out (coalesced), fused softmax-agg
    const float t = *t_ptr;
    const float4* par4 = (const float4*)par;
#pragma unroll
    for (int j = tid; j < 128 * 32; j += 256) {
        int el = j >> 5, q = j & 31;
        int eid = e0 + el;
        if (eid < E_EDGES) {
            float4 es = ((float4*)Es)[el * ES4 + q];
            float mu = mu_s[el], rs = rs_s[el];
            float4 g = par4[32 + q], b = par4[64 + q];
            float4 ea = ((const float4*)edge_attr)[(size_t)eid * 32 + q];
            float4 e;
            e.x = (es.x - mu) * rs * g.x + b.x + ea.x;
            e.y = (es.y - mu) * rs * g.y + b.y + ea.y;
            e.z = (es.z - mu) * rs * g.z + b.z + ea.z;
            e.w = (es.w - mu) * rs * g.w + b.w + ea.w;
            ((float4*)e_out)[(size_t)eid * 32 + q] = e;
            float4 xv = ((const float4*)x)[(size_t)erow_s[el] * 32 + q];
            float m0 = fmaxf(xv.x + e.x, 0.f) + 1e-7f;
            float m1 = fmaxf(xv.y + e.y, 0.f) + 1e-7f;
            float m2 = fmaxf(xv.z + e.z, 0.f) + 1e-7f;
            float m3 = fmaxf(xv.w + e.w, 0.f) + 1e-7f;
            float x0 = __expf(m0 * t), x1 = __expf(m1 * t);
            float x2 = __expf(m2 * t), x3 = __expf(m3 * t);
            float* base = (float*)(g_dn + (size_t)ecol_s[el] * 128 + q * 4);
            red_v4(base,     x0, m0 * x0, x1, m1 * x1);
            red_v4(base + 4, x2, m2 * x2, x3, m3 * x3);
        }
    }
}

// ---------------- mlp1 (grid (196,2)) ----------------------------------------
__global__ __launch_bounds__(256, 2)
void mlp1_tc(const float* __restrict__ x, const float* __restrict__ b_m1)
{
    extern __shared__ __align__(128) char smem[];
    const int tid = threadIdx.x, wid = tid >> 5, lane = tid & 31;
    const int r0 = blockIdx.x * 128;
    const int by = blockIdx.y;          // noff = by*128
    const int wm = wid >> 1, wn = wid & 1;

    float* par = (float*)(smem + SM_PAR);
    if (tid < 128) par[tid] = b_m1[by * 128 + tid];
    __syncthreads();

    uint32_t* AB = (uint32_t*)(smem + SM_AB);
    uint32_t* BB = (uint32_t*)(smem + SM_BB);

    float acc[2][8][4];
#pragma unroll
    for (int mt = 0; mt < 2; ++mt)
#pragma unroll
        for (int nt = 0; nt < 8; ++nt)
#pragma unroll
            for (int q = 0; q < 4; ++q) acc[mt][nt][q] = 0.f;

    for (int c = 0; c < 2; ++c) {
        if (c) __syncthreads();
        {
            int row = tid >> 1, half = tid & 1;
            int r = min(r0 + row, N_NODES - 1);
            int col0 = c * 64 + half * 32;
            const float4* xs  = (const float4*)(x + (size_t)r * 128 + col0);
            const float4* dn4 = (const float4*)(g_dn + (size_t)r * 128 + col0);
            int base = row * SP + half * 16;
#pragma unroll
            for (int i = 0; i < 8; ++i) {
                float4 v = xs[i];
                float4 p0 = dn4[i * 2], p1 = dn4[i * 2 + 1];
                v.x += (p0.x > 0.f) ? p0.y / p0.x : 0.f;
                v.y += (p0.z > 0.f) ? p0.w / p0.z : 0.f;
                v.z += (p1.x > 0.f) ? p1.y / p1.x : 0.f;
                v.w += (p1.z > 0.f) ? p1.w / p1.z : 0.f;
                uint32_t h0, h1, l0, l1;
                split4(v, h0, h1, l0, l1);
                store_a(AB, base + i * 2, h0, h1, l0, l1);
            }
        }
        {
            const uint4* s = (const uint4*)(g_W1 + (size_t)(by * 2 + c) * (128 * SP * 2));
            uint4* d = (uint4*)BB;
#pragma unroll
            for (int j = tid; j < NB4; j += 256) d[j] = s[j];
        }
        __syncthreads();
        mma_chunk(AB, BB, acc, wm, wn, lane);
    }
    // epilogue: bias, store g_h1, BN stats (shfl-reduced)
    const int rbase = r0 + wm * 32 + (lane >> 2);
#pragma unroll
    for (int nt = 0; nt < 8; ++nt) {
        int pc = wn * 64 + nt * 8 + ((lane & 3) << 1);
        int cc = by * 128 + pc;
        float b0 = par[pc], b1 = par[pc + 1];
        float s0 = 0.f, q0 = 0.f, s1 = 0.f, q1 = 0.f;
#pragma unroll
        for (int mt = 0; mt < 2; ++mt) {
            int r1 = rbase + mt * 16, r2 = r1 + 8;
            if (r1 < N_NODES) {
                float a0 = acc[mt][nt][0] + b0, a1 = acc[mt][nt][1] + b1;
                *(float2*)&g_h1[(size_t)r1 * 256 + cc] = make_float2(a0, a1);
                s0 += a0; q0 += a0 * a0; s1 += a1; q1 += a1 * a1;
            }
            if (r2 < N_NODES) {
                float a2 = acc[mt][nt][2] + b0, a3 = acc[mt][nt][3] + b1;
                *(float2*)&g_h1[(size_t)r2 * 256 + cc] = make_float2(a2, a3);
                s0 += a2; q0 += a2 * a2; s1 += a3; q1 += a3 * a3;
            }
        }
#pragma unroll
        for (int o = 4; o < 32; o <<= 1) {
            s0 += __shfl_down_sync(0xffffffffu, s0, o);
            q0 += __shfl_down_sync(0xffffffffu, q0, o);
            s1 += __shfl_down_sync(0xffffffffu, s1, o);
            q1 += __shfl_down_sync(0xffffffffu, q1, o);
        }
        if (lane < 4) {
            atomicAdd(&g_bnstat[cc],     make_float2(s0, q0));
            atomicAdd(&g_bnstat[cc + 1], make_float2(s1, q1));
        }
    }
}

// ------ mlp2 on HMMA (K=256) + inline BN finalize + fused node tail ---------
__global__ __launch_bounds__(256, 2)
void mlp2_tc(const float* __restrict__ x, const float* __restrict__ b_m2,
             const float* __restrict__ scale_ptr, const float* __restrict__ g_n,
             const float* __restrict__ b_n, const float* __restrict__ g_bn,
             const float* __restrict__ b_bn, float* __restrict__ xout)
{
    extern __shared__ __align__(128) char smem[];
    const int tid = threadIdx.x, wid = tid >> 5, lane = tid & 31;
    const int r0 = blockIdx.x * 128;
    const int wm = wid >> 1, wn = wid & 1;

    float* sc  = (float*)(smem + M2_SC);
    float* sh  = (float*)(smem + M2_SH);
    float* bm2 = (float*)(smem + M2_BM2);
    float* gn  = (float*)(smem + M2_GN);
    float* bnn = (float*)(smem + M2_BNN);
    float* ssc = (float*)(smem + M2_SSC);
    float* crw = (float*)(smem + M2_CRW);
    float* muw = (float*)(smem + M2_MUW);
    float* rsw = (float*)(smem + M2_RSW);

    // inline bn_finalize
    {
        float2 st = g_bnstat[tid];
        float mean = st.x * (1.f / N_NODES);
        float var = st.y * (1.f / N_NODES) - mean * mean;
        float a = rsqrtf(var + 1e-5f) * g_bn[tid];
        sc[tid] = a;
        sh[tid] = b_bn[tid] - mean * a;
    }
    if (tid < 128) { bm2[tid] = b_m2[tid]; gn[tid] = g_n[tid]; bnn[tid] = b_n[tid]; }
    if (tid == 0) ssc[0] = *scale_ptr;
    __syncthreads();

    uint32_t* AB = (uint32_t*)(smem + SM_AB);
    uint32_t* BB = (uint32_t*)(smem + SM_BB);

    float acc[2][8][4];
#pragma unroll
    for (int mt = 0; mt < 2; ++mt)
#pragma unroll
        for (int nt = 0; nt < 8; ++nt)
#pragma unroll
            for (int q = 0; q < 4; ++q) acc[mt][nt][q] = 0.f;

    for (int c = 0; c < 4; ++c) {
        if (c) __syncthreads();
        {
            int row = tid >> 1, half = tid & 1;
            int r = min(r0 + row, N_NODES - 1);
            int col0 = c * 64 + half * 32;
            const float4* src = (const float4*)(g_h1 + (size_t)r * 256 + col0);
            const float4* sc4 = (const float4*)sc + (col0 >> 2);
            const float4* sh4 = (const float4*)sh + (col0 >> 2);
            int base = row * SP + half * 16;
#pragma unroll
            for (int i = 0; i < 8; ++i) {
                float4 v = src[i];
                float4 a = sc4[i], b = sh4[i];
                v.x = fmaxf(v.x * a.x + b.x, 0.f);
                v.y = fmaxf(v.y * a.y + b.y, 0.f);
                v.z = fmaxf(v.z * a.z + b.z, 0.f);
                v.w = fmaxf(v.w * a.w + b.w, 0.f);
                uint32_t h0, h1, l0, l1;
                split4(v, h0, h1, l0, l1);
                store_a(AB, base + i * 2, h0, h1, l0, l1);
            }
        }
        {
            const uint4* s = (const uint4*)(g_W2 + (size_t)c * (128 * SP * 2));
            uint4* d = (uint4*)BB;
#pragma unroll
            for (int j = tid; j < NB4; j += 256) d[j] = s[j];
        }
        __syncthreads();
        mma_chunk(AB, BB, acc, wm, wn, lane);
    }
    __syncthreads();

    float* Es = (float*)(smem + SM_ES);
#pragma unroll
    for (int mt = 0; mt < 2; ++mt) {
        int r = wm * 32 + mt * 16 + (lane >> 2);
#pragma unroll
        for (int nt = 0; nt < 8; ++nt) {
            int cc = wn * 64 + nt * 8 + ((lane & 3) << 1);
            Es[r * ESW + cc]           = acc[mt][nt][0];
            Es[r * ESW + cc + 1]       = acc[mt][nt][1];
            Es[(r + 8) * ESW + cc]     = acc[mt][nt][2];
            Es[(r + 8) * ESW + cc + 1] = acc[mt][nt][3];
        }
    }
    __syncthreads();

    // Phase A: bias; 5 moments (h,x) -> exact LN(x + c*h) stats
    {
        int el = tid >> 1, h = tid & 1;
        int node = r0 + el;
        float4* Es4 = (float4*)Es;
        const float4* bm24 = (const float4*)bm2;
        float Sh = 0.f, Shh = 0.f, Sx = 0.f, Sxx = 0.f, Sxh = 0.f;
        if (node < N_NODES) {
            const float4* x4 = (const float4*)(x + (size_t)node * 128);
#pragma unroll
            for (int i = 0; i < 16; ++i) {
                int q = i * 2 + h;
                float4 hv = Es4[el * ES4 + q];
                float4 bb = bm24[q];
                hv.x += bb.x; hv.y += bb.y; hv.z += bb.z; hv.w += bb.w;
                Es4[el * ES4 + q] = hv;
                float4 xv = x4[q];
                Sh  += hv.x + hv.y + hv.z + hv.w;
                Shh += hv.x * hv.x + hv.y * hv.y + hv.z * hv.z + hv.w * hv.w;
                Sx  += xv.x + xv.y + xv.z + xv.w;
                Sxx += xv.x * xv.x + xv.y * xv.y + xv.z * xv.z + xv.w * xv.w;
                Sxh += hv.x * xv.x + hv.y * xv.y + hv.z * xv.z + hv.w * xv.w;
            }
        }
        Sh  += __shfl_xor_sync(0xffffffffu, Sh, 1);
        Shh += __shfl_xor_sync(0xffffffffu, Shh, 1);
        Sx  += __shfl_xor_sync(0xffffffffu, Sx, 1);
        Sxx += __shfl_xor_sync(0xffffffffu, Sxx, 1);
        Sxh += __shfl_xor_sync(0xffffffffu, Sxh, 1);
        if (h == 0 && node < N_NODES) {
            float hn = sqrtf(Shh), xn = sqrtf(Sxx);
            float cr = xn * ssc[0] / fmaxf(hn, 1e-12f);
            float mu = (Sx + cr * Sh) * (1.f / 128.f);
            float var = (Sxx + 2.f * cr * Sxh + cr * cr * Shh) * (1.f / 128.f) - mu * mu;
            crw[el] = cr; muw[el] = mu; rsw[el] = rsqrtf(var + 1e-5f);
        }
    }
    __syncthreads();

    // Phase B: out = (x + c*h - mu)*rs*g_n + b_n  (coalesced)
#pragma unroll
    for (int j = tid; j < 128 * 32; j += 256) {
        int el = j >> 5, q = j & 31;
        int node = r0 + el;
        if (node < N_NODES) {
            float4 hv = ((float4*)Es)[el * ES4 + q];
            float4 xv = ((const float4*)x)[(size_t)node * 32 + q];
            float cr = crw[el], mu = muw[el], rs = rsw[el];
            float4 g = ((const float4*)gn)[q], b = ((const float4*)bnn)[q];
            float4 o;
            o.x = (xv.x + cr * hv.x - mu) * rs * g.x + b.x;
            o.y = (xv.y + cr * hv.y - mu) * rs * g.y + b.y;
            o.z = (xv.z + cr * hv.z - mu) * rs * g.z + b.z;
            o.w = (xv.w + cr * hv.w - mu) * rs * g.w + b.w;
            ((float4*)xout)[(size_t)node * 32 + q] = o;
        }
    }
}

// ---------------- launch ------------------------------------------------------
extern "C" void kernel_launch(void* const* d_in, const int* in_sizes, int n_in,
                              void* d_out, int out_size)
{
    const float* x        = (const float*)d_in[0];
    const float* edge_attr= (const float*)d_in[1];
    const int*   eidx     = (const int*)  d_in[2];
    const float* W_e      = (const float*)d_in[3];
    const float* b_e      = (const float*)d_in[4];
    const float* g_e      = (const float*)d_in[5];
    const float* be_e     = (const float*)d_in[6];
    const float* t        = (const float*)d_in[7];
    const float* W_m1     = (const float*)d_in[8];
    const float* b_m1     = (const float*)d_in[9];
    const float* g_bn     = (const float*)d_in[10];
    const float* b_bn     = (const float*)d_in[11];
    const float* W_m2     = (const float*)d_in[12];
    const float* b_m2     = (const float*)d_in[13];
    const float* scale    = (const float*)d_in[14];
    const float* g_n      = (const float*)d_in[15];
    const float* b_n      = (const float*)d_in[16];
    const int* erow = eidx;
    const int* ecol = eidx + E_EDGES;
    float* xout  = (float*)d_out;
    float* e_out = (float*)d_out + (size_t)N_NODES * DD;

    cudaFuncSetAttribute((const void*)node_pre_kernel,
                         cudaFuncAttributeMaxDynamicSharedMemorySize, SM_TOTAL_TC);
    cudaFuncSetAttribute((const void*)edge_mlp_tc,
                         cudaFuncAttributeMaxDynamicSharedMemorySize, SM_TOTAL_TC);
    cudaFuncSetAttribute((const void*)mlp1_tc,
                         cudaFuncAttributeMaxDynamicSharedMemorySize, SM_TOTAL_TC);
    cudaFuncSetAttribute((const void*)mlp2_tc,
                         cudaFuncAttributeMaxDynamicSharedMemorySize, SM_TOTAL_TC);

    prep_kernel<<<(384 * 128 + 128 * 256 + 256 * 128 + 255) / 256, 256>>>(W_e, W_m1, W_m2);
    dim3 gn2((N_NODES + 127) / 128, 2);
    node_pre_kernel<<<gn2, 256, SM_TOTAL_TC>>>(x);
    edge_mlp_tc<<<(E_EDGES + 127) / 128, 256, SM_TOTAL_TC>>>(
        x, edge_attr, erow, ecol, b_e, g_e, be_e, t, e_out);
    mlp1_tc<<<gn2, 256, SM_TOTAL_TC>>>(x, b_m1);
    mlp2_tc<<<(N_NODES + 127) / 128, 256, SM_TOTAL_TC>>>(
        x, b_m2, scale, g_n, b_n, g_bn, b_bn, xout);
}

// round 16
// speedup vs baseline: 1.0797x; 1.0797x over previous
#include <cuda_runtime.h>
#include <cuda_bf16.h>
#include <math.h>
#include <stdint.h>

#define N_NODES 25000
#define E_EDGES 250000
#define DD 128

// ---------------- scratch ----------------------------------------------------
__device__ float2 g_dn[(size_t)N_NODES * DD];        // (denom, numerator)
__device__ float  g_xw[(size_t)N_NODES * 256];       // [xW1 | xW2] per node
__device__ float  g_h1[(size_t)N_NODES * 2 * DD];    // after first MLP linear
__device__ float2 g_bnstat[2 * DD];                  // (sum, sumsq)
// INTERLEAVED bf16 weight images: u32 idx 2e = hi(e), 2e+1 = lo(e); rows [n][SP]
#define KP 72
#define SP (KP / 2)      // logical u32 row stride = 36 (conflict-free)
__device__ uint32_t g_We[6 * 128 * SP * 2];          // W_e^T, 6 images
__device__ uint32_t g_W1[4 * 128 * SP * 2];          // W_m1^T, 4 images
__device__ uint32_t g_W2[4 * 128 * SP * 2];          // W_m2^T, 4 images

// ---------------- prep: weights -> transposed split interleaved images -------
__global__ void prep_kernel(const float* __restrict__ W_e,
                            const float* __restrict__ W_m1,
                            const float* __restrict__ W_m2) {
    int i = blockIdx.x * 256 + threadIdx.x;
    float v; int idx; uint32_t* arr;
    if (i < 384 * 128) {
        int k = i >> 7, n = i & 127;
        v = W_e[i];
        idx = (((k >> 6) * 128) + n) * KP + (k & 63);
        arr = g_We;
    } else if (i < 384 * 128 + 128 * 256) {
        int j = i - 384 * 128;
        int k = j >> 8, n = j & 255;
        v = W_m1[j];
        int g = ((n >> 7) << 1) + (k >> 6);
        idx = (g * 128 + (n & 127)) * KP + (k & 63);
        arr = g_W1;
    } else if (i < 384 * 128 + 128 * 256 + 256 * 128) {
        int j = i - (384 * 128 + 128 * 256);
        int k = j >> 7, n = j & 127;
        v = W_m2[j];
        idx = (((k >> 6) * 128) + n) * KP + (k & 63);
        arr = g_W2;
    } else return;
    __nv_bfloat16 h = __float2bfloat16(v);
    __nv_bfloat16 l = __float2bfloat16(v - __bfloat162float(h));
    int e = idx >> 1, hh = idx & 1;
    unsigned short* p = (unsigned short*)arr;
    p[4 * e + hh]     = __bfloat16_as_ushort(h);
    p[4 * e + 2 + hh] = __bfloat16_as_ushort(l);
}

// ---------------- HMMA machinery ---------------------------------------------
__device__ __forceinline__ void mma_bf16(float* d, const uint32_t* a,
                                         uint32_t b0, uint32_t b1) {
    asm volatile(
        "mma.sync.aligned.m16n8k16.row.col.f32.bf16.bf16.f32 "
        "{%0,%1,%2,%3}, {%4,%5,%6,%7}, {%8,%9}, {%0,%1,%2,%3};"
        : "+f"(d[0]), "+f"(d[1]), "+f"(d[2]), "+f"(d[3])
        : "r"(a[0]), "r"(a[1]), "r"(a[2]), "r"(a[3]), "r"(b0), "r"(b1));
}

__device__ __forceinline__ void red_v4(float* gp, float a, float b, float c, float d) {
    asm volatile("red.global.add.v4.f32 [%0], {%1,%2,%3,%4};"
                 :: "l"(gp), "f"(a), "f"(b), "f"(c), "f"(d) : "memory");
}

__device__ __forceinline__ void split4(float4 v, uint32_t& h0, uint32_t& h1,
                                       uint32_t& l0, uint32_t& l1) {
    __nv_bfloat16 a0 = __float2bfloat16(v.x), a1 = __float2bfloat16(v.y);
    __nv_bfloat16 a2 = __float2bfloat16(v.z), a3 = __float2bfloat16(v.w);
    __nv_bfloat16 b0 = __float2bfloat16(v.x - __bfloat162float(a0));
    __nv_bfloat16 b1 = __float2bfloat16(v.y - __bfloat162float(a1));
    __nv_bfloat16 b2 = __float2bfloat16(v.z - __bfloat162float(a2));
    __nv_bfloat16 b3 = __float2bfloat16(v.w - __bfloat162float(a3));
    h0 = (uint32_t)__bfloat16_as_ushort(a0) | ((uint32_t)__bfloat16_as_ushort(a1) << 16);
    h1 = (uint32_t)__bfloat16_as_ushort(a2) | ((uint32_t)__bfloat16_as_ushort(a3) << 16);
    l0 = (uint32_t)__bfloat16_as_ushort(b0) | ((uint32_t)__bfloat16_as_ushort(b1) << 16);
    l1 = (uint32_t)__bfloat16_as_ushort(b2) | ((uint32_t)__bfloat16_as_ushort(b3) << 16);
}

// fragment-reuse 3-term MMA: A from separate hi/lo (R14), B via LDS.64 pairs
__device__ __forceinline__ void mma_chunk(const uint32_t* Ahi, const uint32_t* Alo,
                                          const uint32_t* BB,
                                          float acc[2][8][4], int wm, int wn, int lane) {
#pragma unroll
    for (int ks = 0; ks < 4; ++ks) {
        const int kb = ks * 8;
        uint32_t ah[2][4], al[2][4];
#pragma unroll
        for (int mt = 0; mt < 2; ++mt) {
            int ar = wm * 32 + mt * 16 + (lane >> 2);
            int ac = kb + (lane & 3);
            ah[mt][0] = Ahi[ar * SP + ac];
            ah[mt][1] = Ahi[(ar + 8) * SP + ac];
            ah[mt][2] = Ahi[ar * SP + ac + 4];
            ah[mt][3] = Ahi[(ar + 8) * SP + ac + 4];
            al[mt][0] = Alo[ar * SP + ac];
            al[mt][1] = Alo[(ar + 8) * SP + ac];
            al[mt][2] = Alo[ar * SP + ac + 4];
            al[mt][3] = Alo[(ar + 8) * SP + ac + 4];
        }
#pragma unroll
        for (int nt = 0; nt < 8; ++nt) {
            int bo = (wn * 64 + nt * 8 + (lane >> 2)) * SP + kb + (lane & 3);
            uint2 bp0 = *(const uint2*)&BB[bo * 2];        // (bh0, bl0)
            uint2 bp1 = *(const uint2*)&BB[(bo + 4) * 2];  // (bh1, bl1)
            mma_bf16(acc[0][nt], ah[0], bp0.x, bp1.x);
            mma_bf16(acc[1][nt], ah[1], bp0.x, bp1.x);
            mma_bf16(acc[0][nt], ah[0], bp0.y, bp1.y);
            mma_bf16(acc[1][nt], ah[1], bp0.y, bp1.y);
            mma_bf16(acc[0][nt], al[0], bp0.x, bp1.x);
            mma_bf16(acc[1][nt], al[1], bp0.x, bp1.x);
        }
    }
}

// smem layout (bytes): A hi/lo separate (R14), B interleaved (single buffer)
#define SM_IDX  0
#define SM_PAR  1024
#define SM_MUR  2560       // mu[128], rstd[128]
#define SM_AHI  4096
#define SM_ALO  (SM_AHI + 18432)
#define SM_BB   (SM_ALO + 18432)              // interleaved B: 36864 B
#define SM_ES   SM_AHI
#define ESW     132
#define ES4     33
#define SM_TOTAL_TC (SM_BB + 36864)           // 77824 -> 2 CTAs/SM
#define NB4     (128 * SP / 2)                // uint4 count per B image = 2304
// mlp2 params: low region (0..4096) + dead B-tail (71680..77824)
#define M2_SC   0
#define M2_SH   1024
#define M2_BM2  2048
#define M2_GN   2560
#define M2_BNN  3072
#define M2_SSC  3584
#define M2_CRW  71680
#define M2_MUW  72192
#define M2_RSW  72704

// ---------------- node precompute (folded init) ------------------------------
__global__ __launch_bounds__(256, 2)
void node_pre_kernel(const float* __restrict__ x)
{
    extern __shared__ __align__(128) char smem[];
    const int tid = threadIdx.x, wid = tid >> 5, lane = tid & 31;
    const int r0 = blockIdx.x * 128;
    const int by = blockIdx.y;
    const int wm = wid >> 1, wn = wid & 1;

    // folded init: zero g_dn + bnstat across all blocks
    {
        int nb = gridDim.x * 2;
        int bid = blockIdx.y * gridDim.x + blockIdx.x;
        size_t total = (size_t)N_NODES * DD;
        size_t per = (total + nb - 1) / nb;
        size_t s = (size_t)bid * per;
        size_t e = s + per; if (e > total) e = total;
        for (size_t i = s + tid; i < e; i += 256) g_dn[i] = make_float2(0.f, 0.f);
        if (bid == 0 && tid < 2 * DD) g_bnstat[tid] = make_float2(0.f, 0.f);
    }

    uint32_t* Ahi = (uint32_t*)(smem + SM_AHI);
    uint32_t* Alo = (uint32_t*)(smem + SM_ALO);
    uint32_t* BB  = (uint32_t*)(smem + SM_BB);

    float acc[2][8][4];
#pragma unroll
    for (int mt = 0; mt < 2; ++mt)
#pragma unroll
        for (int nt = 0; nt < 8; ++nt)
#pragma unroll
            for (int q = 0; q < 4; ++q) acc[mt][nt][q] = 0.f;

    for (int c = 0; c < 2; ++c) {
        if (c) __syncthreads();
        {
            int row = tid >> 1, half = tid & 1;
            int r = min(r0 + row, N_NODES - 1);
            const float4* src = (const float4*)(x + (size_t)r * 128 + c * 64 + half * 32);
            int base = row * SP + half * 16;
#pragma unroll
            for (int i = 0; i < 8; ++i) {
                uint32_t h0, h1, l0, l1;
                split4(src[i], h0, h1, l0, l1);
                Ahi[base + i * 2] = h0; Ahi[base + i * 2 + 1] = h1;
                Alo[base + i * 2] = l0; Alo[base + i * 2 + 1] = l1;
            }
        }
        {
            const uint4* s = (const uint4*)(g_We + (size_t)(by * 2 + c) * (128 * SP * 2));
            uint4* d = (uint4*)BB;
#pragma unroll
            for (int j = tid; j < NB4; j += 256) d[j] = s[j];
        }
        __syncthreads();
        mma_chunk(Ahi, Alo, BB, acc, wm, wn, lane);
    }
#pragma unroll
    for (int mt = 0; mt < 2; ++mt) {
        int r = r0 + wm * 32 + mt * 16 + (lane >> 2);
#pragma unroll
        for (int nt = 0; nt < 8; ++nt) {
            int cc = by * 128 + wn * 64 + nt * 8 + ((lane & 3) << 1);
            if (r < N_NODES)
                *(float2*)&g_xw[(size_t)r * 256 + cc] = make_float2(acc[mt][nt][0], acc[mt][nt][1]);
            if (r + 8 < N_NODES)
                *(float2*)&g_xw[(size_t)(r + 8) * 256 + cc] = make_float2(acc[mt][nt][2], acc[mt][nt][3]);
        }
    }
}

// ---------------- edge kernel ------------------------------------------------
__global__ __launch_bounds__(256, 2)
void edge_mlp_tc(const float* __restrict__ x, const float* __restrict__ edge_attr,
                 const int* __restrict__ erow, const int* __restrict__ ecol,
                 const float* __restrict__ b_e, const float* __restrict__ g_e,
                 const float* __restrict__ be_e, const float* __restrict__ t_ptr,
                 float* __restrict__ e_out)
{
    extern __shared__ __align__(128) char smem[];
    const int tid = threadIdx.x, wid = tid >> 5, lane = tid & 31;
    const int e0 = blockIdx.x * 128;
    const int wm = wid >> 1, wn = wid & 1;

    int*   erow_s = (int*)(smem + SM_IDX);
    int*   ecol_s = erow_s + 128;
    float* par    = (float*)(smem + SM_PAR);
    float* mu_s   = (float*)(smem + SM_MUR);
    float* rs_s   = mu_s + 128;

    if (tid < 128) {
        int eid = min(e0 + tid, E_EDGES - 1);
        erow_s[tid] = erow[eid];
        ecol_s[tid] = ecol[eid];
        par[tid]       = b_e[tid];
        par[128 + tid] = g_e[tid];
        par[256 + tid] = be_e[tid];
    }
    __syncthreads();

    uint32_t* Ahi = (uint32_t*)(smem + SM_AHI);
    uint32_t* Alo = (uint32_t*)(smem + SM_ALO);
    uint32_t* BB  = (uint32_t*)(smem + SM_BB);

    float acc[2][8][4];
#pragma unroll
    for (int mt = 0; mt < 2; ++mt)
#pragma unroll
        for (int nt = 0; nt < 8; ++nt)
#pragma unroll
            for (int q = 0; q < 4; ++q) acc[mt][nt][q] = 0.f;

    for (int c = 0; c < 2; ++c) {
        if (c) __syncthreads();
        {
            int row = tid >> 1, half = tid & 1;
            const float4* src = (const float4*)(edge_attr +
                (size_t)min(e0 + row, E_EDGES - 1) * 128 + c * 64 + half * 32);
            int base = row * SP + half * 16;
#pragma unroll
            for (int i = 0; i < 8; ++i) {
                uint32_t h0, h1, l0, l1;
                split4(src[i], h0, h1, l0, l1);
                Ahi[base + i * 2] = h0; Ahi[base + i * 2 + 1] = h1;
                Alo[base + i * 2] = l0; Alo[base + i * 2 + 1] = l1;
            }
        }
        {
            const uint4* s = (const uint4*)(g_We + (size_t)(4 + c) * (128 * SP * 2));
            uint4* d = (uint4*)BB;
#pragma unroll
            for (int j = tid; j < NB4; j += 256) d[j] = s[j];
        }
        __syncthreads();
        mma_chunk(Ahi, Alo, BB, acc, wm, wn, lane);
    }
    __syncthreads();          // smem -> Es reuse

    float* Es = (float*)(smem + SM_ES);
#pragma unroll
    for (int mt = 0; mt < 2; ++mt) {
        int r = wm * 32 + mt * 16 + (lane >> 2);
#pragma unroll
        for (int nt = 0; nt < 8; ++nt) {
            int cc = wn * 64 + nt * 8 + ((lane & 3) << 1);
            Es[r * ESW + cc]           = acc[mt][nt][0];
            Es[r * ESW + cc + 1]       = acc[mt][nt][1];
            Es[(r + 8) * ESW + cc]     = acc[mt][nt][2];
            Es[(r + 8) * ESW + cc + 1] = acc[mt][nt][3];
        }
    }
    __syncthreads();

    // Phase A: add node precomputes + bias, ReLU, LN stats (2 threads/edge)
    {
        int el = tid >> 1, h = tid & 1;
        float4* Es4 = (float4*)Es;
        const float4* par4 = (const float4*)par;
        const float4* xr4 = (const float4*)(g_xw + (size_t)erow_s[el] * 256);
        const float4* xc4 = (const float4*)(g_xw + (size_t)ecol_s[el] * 256 + 128);
        float s = 0.f, ss = 0.f;
#pragma unroll
        for (int i = 0; i < 16; ++i) {
            int q = i * 2 + h;
            float4 es = Es4[el * ES4 + q];
            float4 bb = par4[q];
            float4 xr = xr4[q];
            float4 xc = xc4[q];
            float4 v;
            v.x = fmaxf(es.x + bb.x + xr.x + xc.x, 0.f);
            v.y = fmaxf(es.y + bb.y + xr.y + xc.y, 0.f);
            v.z = fmaxf(es.z + bb.z + xr.z + xc.z, 0.f);
            v.w = fmaxf(es.w + bb.w + xr.w + xc.w, 0.f);
            Es4[el * ES4 + q] = v;
            s += v.x + v.y + v.z + v.w;
            ss += v.x * v.x + v.y * v.y + v.z * v.z + v.w * v.w;
        }
        s  += __shfl_xor_sync(0xffffffffu, s, 1);
        ss += __shfl_xor_sync(0xffffffffu, ss, 1);
        float mu = s * (1.f / 128.f);
        mu_s[el] = mu;
        rs_s[el] = rsqrtf(ss * (1.f / 128.f) - mu * mu + 1e-5f);
    }
    __syncthreads();

    // Phase B: normalize + residual -> e_out (coalesced), fused softmax-agg
    const float t = *t_ptr;
    const float4* par4 = (const float4*)par;
#pragma unroll
    for (int j = tid; j < 128 * 32; j += 256) {
        int el = j >> 5, q = j & 31;
        int eid = e0 + el;
        if (eid < E_EDGES) {
            float4 es = ((float4*)Es)[el * ES4 + q];
            float mu = mu_s[el], rs = rs_s[el];
            float4 g = par4[32 + q], b = par4[64 + q];
            float4 ea = ((const float4*)edge_attr)[(size_t)eid * 32 + q];
            float4 e;
            e.x = (es.x - mu) * rs * g.x + b.x + ea.x;
            e.y = (es.y - mu) * rs * g.y + b.y + ea.y;
            e.z = (es.z - mu) * rs * g.z + b.z + ea.z;
            e.w = (es.w - mu) * rs * g.w + b.w + ea.w;
            ((float4*)e_out)[(size_t)eid * 32 + q] = e;
            float4 xv = ((const float4*)x)[(size_t)erow_s[el] * 32 + q];
            float m0 = fmaxf(xv.x + e.x, 0.f) + 1e-7f;
            float m1 = fmaxf(xv.y + e.y, 0.f) + 1e-7f;
            float m2 = fmaxf(xv.z + e.z, 0.f) + 1e-7f;
            float m3 = fmaxf(xv.w + e.w, 0.f) + 1e-7f;
            float x0 = __expf(m0 * t), x1 = __expf(m1 * t);
            float x2 = __expf(m2 * t), x3 = __expf(m3 * t);
            float* base = (float*)(g_dn + (size_t)ecol_s[el] * 128 + q * 4);
            red_v4(base,     x0, m0 * x0, x1, m1 * x1);
            red_v4(base + 4, x2, m2 * x2, x3, m3 * x3);
        }
    }
}

// ---------------- mlp1 (grid (196,2)) ----------------------------------------
__global__ __launch_bounds__(256, 2)
void mlp1_tc(const float* __restrict__ x, const float* __restrict__ b_m1)
{
    extern __shared__ __align__(128) char smem[];
    const int tid = threadIdx.x, wid = tid >> 5, lane = tid & 31;
    const int r0 = blockIdx.x * 128;
    const int by = blockIdx.y;          // noff = by*128
    const int wm = wid >> 1, wn = wid & 1;

    float* par = (float*)(smem + SM_PAR);
    if (tid < 128) par[tid] = b_m1[by * 128 + tid];
    __syncthreads();

    uint32_t* Ahi = (uint32_t*)(smem + SM_AHI);
    uint32_t* Alo = (uint32_t*)(smem + SM_ALO);
    uint32_t* BB  = (uint32_t*)(smem + SM_BB);

    float acc[2][8][4];
#pragma unroll
    for (int mt = 0; mt < 2; ++mt)
#pragma unroll
        for (int nt = 0; nt < 8; ++nt)
#pragma unroll
            for (int q = 0; q < 4; ++q) acc[mt][nt][q] = 0.f;

    for (int c = 0; c < 2; ++c) {
        if (c) __syncthreads();
        {
            int row = tid >> 1, half = tid & 1;
            int r = min(r0 + row, N_NODES - 1);
            int col0 = c * 64 + half * 32;
            const float4* xs  = (const float4*)(x + (size_t)r * 128 + col0);
            const float4* dn4 = (const float4*)(g_dn + (size_t)r * 128 + col0);
            int base = row * SP + half * 16;
#pragma unroll
            for (int i = 0; i < 8; ++i) {
                float4 v = xs[i];
                float4 p0 = dn4[i * 2], p1 = dn4[i * 2 + 1];
                v.x += (p0.x > 0.f) ? p0.y / p0.x : 0.f;
                v.y += (p0.z > 0.f) ? p0.w / p0.z : 0.f;
                v.z += (p1.x > 0.f) ? p1.y / p1.x : 0.f;
                v.w += (p1.z > 0.f) ? p1.w / p1.z : 0.f;
                uint32_t h0, h1, l0, l1;
                split4(v, h0, h1, l0, l1);
                Ahi[base + i * 2] = h0; Ahi[base + i * 2 + 1] = h1;
                Alo[base + i * 2] = l0; Alo[base + i * 2 + 1] = l1;
            }
        }
        {
            const uint4* s = (const uint4*)(g_W1 + (size_t)(by * 2 + c) * (128 * SP * 2));
            uint4* d = (uint4*)BB;
#pragma unroll
            for (int j = tid; j < NB4; j += 256) d[j] = s[j];
        }
        __syncthreads();
        mma_chunk(Ahi, Alo, BB, acc, wm, wn, lane);
    }
    // epilogue: bias, store g_h1, BN stats (shfl-reduced)
    const int rbase = r0 + wm * 32 + (lane >> 2);
#pragma unroll
    for (int nt = 0; nt < 8; ++nt) {
        int pc = wn * 64 + nt * 8 + ((lane & 3) << 1);
        int cc = by * 128 + pc;
        float b0 = par[pc], b1 = par[pc + 1];
        float s0 = 0.f, q0 = 0.f, s1 = 0.f, q1 = 0.f;
#pragma unroll
        for (int mt = 0; mt < 2; ++mt) {
            int r1 = rbase + mt * 16, r2 = r1 + 8;
            if (r1 < N_NODES) {
                float a0 = acc[mt][nt][0] + b0, a1 = acc[mt][nt][1] + b1;
                *(float2*)&g_h1[(size_t)r1 * 256 + cc] = make_float2(a0, a1);
                s0 += a0; q0 += a0 * a0; s1 += a1; q1 += a1 * a1;
            }
            if (r2 < N_NODES) {
                float a2 = acc[mt][nt][2] + b0, a3 = acc[mt][nt][3] + b1;
                *(float2*)&g_h1[(size_t)r2 * 256 + cc] = make_float2(a2, a3);
                s0 += a2; q0 += a2 * a2; s1 += a3; q1 += a3 * a3;
            }
        }
#pragma unroll
        for (int o = 4; o < 32; o <<= 1) {
            s0 += __shfl_down_sync(0xffffffffu, s0, o);
            q0 += __shfl_down_sync(0xffffffffu, q0, o);
            s1 += __shfl_down_sync(0xffffffffu, s1, o);
            q1 += __shfl_down_sync(0xffffffffu, q1, o);
        }
        if (lane < 4) {
            atomicAdd(&g_bnstat[cc],     make_float2(s0, q0));
            atomicAdd(&g_bnstat[cc + 1], make_float2(s1, q1));
        }
    }
}

// ------ mlp2 on HMMA (K=256) + inline BN finalize + fused node tail ---------
__global__ __launch_bounds__(256, 2)
void mlp2_tc(const float* __restrict__ x, const float* __restrict__ b_m2,
             const float* __restrict__ scale_ptr, const float* __restrict__ g_n,
             const float* __restrict__ b_n, const float* __restrict__ g_bn,
             const float* __restrict__ b_bn, float* __restrict__ xout)
{
    extern __shared__ __align__(128) char smem[];
    const int tid = threadIdx.x, wid = tid >> 5, lane = tid & 31;
    const int r0 = blockIdx.x * 128;
    const int wm = wid >> 1, wn = wid & 1;

    float* sc  = (float*)(smem + M2_SC);
    float* sh  = (float*)(smem + M2_SH);
    float* bm2 = (float*)(smem + M2_BM2);
    float* gn  = (float*)(smem + M2_GN);
    float* bnn = (float*)(smem + M2_BNN);
    float* ssc = (float*)(smem + M2_SSC);
    float* crw = (float*)(smem + M2_CRW);
    float* muw = (float*)(smem + M2_MUW);
    float* rsw = (float*)(smem + M2_RSW);

    // inline bn_finalize
    {
        float2 st = g_bnstat[tid];
        float mean = st.x * (1.f / N_NODES);
        float var = st.y * (1.f / N_NODES) - mean * mean;
        float a = rsqrtf(var + 1e-5f) * g_bn[tid];
        sc[tid] = a;
        sh[tid] = b_bn[tid] - mean * a;
    }
    if (tid < 128) { bm2[tid] = b_m2[tid]; gn[tid] = g_n[tid]; bnn[tid] = b_n[tid]; }
    if (tid == 0) ssc[0] = *scale_ptr;
    __syncthreads();

    uint32_t* Ahi = (uint32_t*)(smem + SM_AHI);
    uint32_t* Alo = (uint32_t*)(smem + SM_ALO);
    uint32_t* BB  = (uint32_t*)(smem + SM_BB);

    float acc[2][8][4];
#pragma unroll
    for (int mt = 0; mt < 2; ++mt)
#pragma unroll
        for (int nt = 0; nt < 8; ++nt)
#pragma unroll
            for (int q = 0; q < 4; ++q) acc[mt][nt][q] = 0.f;

    for (int c = 0; c < 4; ++c) {
        if (c) __syncthreads();
        {
            int row = tid >> 1, half = tid & 1;
            int r = min(r0 + row, N_NODES - 1);
            int col0 = c * 64 + half * 32;
            const float4* src = (const float4*)(g_h1 + (size_t)r * 256 + col0);
            const float4* sc4 = (const float4*)sc + (col0 >> 2);
            const float4* sh4 = (const float4*)sh + (col0 >> 2);
            int base = row * SP + half * 16;
#pragma unroll
            for (int i = 0; i < 8; ++i) {
                float4 v = src[i];
                float4 a = sc4[i], b = sh4[i];
                v.x = fmaxf(v.x * a.x + b.x, 0.f);
                v.y = fmaxf(v.y * a.y + b.y, 0.f);
                v.z = fmaxf(v.z * a.z + b.z, 0.f);
                v.w = fmaxf(v.w * a.w + b.w, 0.f);
                uint32_t h0, h1, l0, l1;
                split4(v, h0, h1, l0, l1);
                Ahi[base + i * 2] = h0; Ahi[base + i * 2 + 1] = h1;
                Alo[base + i * 2] = l0; Alo[base + i * 2 + 1] = l1;
            }
        }
        {
            const uint4* s = (const uint4*)(g_W2 + (size_t)c * (128 * SP * 2));
            uint4* d = (uint4*)BB;
#pragma unroll
            for (int j = tid; j < NB4; j += 256) d[j] = s[j];
        }
        __syncthreads();
        mma_chunk(Ahi, Alo, BB, acc, wm, wn, lane);
    }
    __syncthreads();

    float* Es = (float*)(smem + SM_ES);
#pragma unroll
    for (int mt = 0; mt < 2; ++mt) {
        int r = wm * 32 + mt * 16 + (lane >> 2);
#pragma unroll
        for (int nt = 0; nt < 8; ++nt) {
            int cc = wn * 64 + nt * 8 + ((lane & 3) << 1);
            Es[r * ESW + cc]           = acc[mt][nt][0];
            Es[r * ESW + cc + 1]       = acc[mt][nt][1];
            Es[(r + 8) * ESW + cc]     = acc[mt][nt][2];
            Es[(r + 8) * ESW + cc + 1] = acc[mt][nt][3];
        }
    }
    __syncthreads();

    // Phase A: bias; 5 moments (h,x) -> exact LN(x + c*h) stats
    {
        int el = tid >> 1, h = tid & 1;
        int node = r0 + el;
        float4* Es4 = (float4*)Es;
        const float4* bm24 = (const float4*)bm2;
        float Sh = 0.f, Shh = 0.f, Sx = 0.f, Sxx = 0.f, Sxh = 0.f;
        if (node < N_NODES) {
            const float4* x4 = (const float4*)(x + (size_t)node * 128);
#pragma unroll
            for (int i = 0; i < 16; ++i) {
                int q = i * 2 + h;
                float4 hv = Es4[el * ES4 + q];
                float4 bb = bm24[q];
                hv.x += bb.x; hv.y += bb.y; hv.z += bb.z; hv.w += bb.w;
                Es4[el * ES4 + q] = hv;
                float4 xv = x4[q];
                Sh  += hv.x + hv.y + hv.z + hv.w;
                Shh += hv.x * hv.x + hv.y * hv.y + hv.z * hv.z + hv.w * hv.w;
                Sx  += xv.x + xv.y + xv.z + xv.w;
                Sxx += xv.x * xv.x + xv.y * xv.y + xv.z * xv.z + xv.w * xv.w;
                Sxh += hv.x * xv.x + hv.y * xv.y + hv.z * xv.z + hv.w * xv.w;
            }
        }
        Sh  += __shfl_xor_sync(0xffffffffu, Sh, 1);
        Shh += __shfl_xor_sync(0xffffffffu, Shh, 1);
        Sx  += __shfl_xor_sync(0xffffffffu, Sx, 1);
        Sxx += __shfl_xor_sync(0xffffffffu, Sxx, 1);
        Sxh += __shfl_xor_sync(0xffffffffu, Sxh, 1);
        if (h == 0 && node < N_NODES) {
            float hn = sqrtf(Shh), xn = sqrtf(Sxx);
            float cr = xn * ssc[0] / fmaxf(hn, 1e-12f);
            float mu = (Sx + cr * Sh) * (1.f / 128.f);
            float var = (Sxx + 2.f * cr * Sxh + cr * cr * Shh) * (1.f / 128.f) - mu * mu;
            crw[el] = cr; muw[el] = mu; rsw[el] = rsqrtf(var + 1e-5f);
        }
    }
    __syncthreads();

    // Phase B: out = (x + c*h - mu)*rs*g_n + b_n  (coalesced)
#pragma unroll
    for (int j = tid; j < 128 * 32; j += 256) {
        int el = j >> 5, q = j & 31;
        int node = r0 + el;
        if (node < N_NODES) {
            float4 hv = ((float4*)Es)[el * ES4 + q];
            float4 xv = ((const float4*)x)[(size_t)node * 32 + q];
            float cr = crw[el], mu = muw[el], rs = rsw[el];
            float4 g = ((const float4*)gn)[q], b = ((const float4*)bnn)[q];
            float4 o;
            o.x = (xv.x + cr * hv.x - mu) * rs * g.x + b.x;
            o.y = (xv.y + cr * hv.y - mu) * rs * g.y + b.y;
            o.z = (xv.z + cr * hv.z - mu) * rs * g.z + b.z;
            o.w = (xv.w + cr * hv.w - mu) * rs * g.w + b.w;
            ((float4*)xout)[(size_t)node * 32 + q] = o;
        }
    }
}

// ---------------- launch ------------------------------------------------------
extern "C" void kernel_launch(void* const* d_in, const int* in_sizes, int n_in,
                              void* d_out, int out_size)
{
    const float* x        = (const float*)d_in[0];
    const float* edge_attr= (const float*)d_in[1];
    const int*   eidx     = (const int*)  d_in[2];
    const float* W_e      = (const float*)d_in[3];
    const float* b_e      = (const float*)d_in[4];
    const float* g_e      = (const float*)d_in[5];
    const float* be_e     = (const float*)d_in[6];
    const float* t        = (const float*)d_in[7];
    const float* W_m1     = (const float*)d_in[8];
    const float* b_m1     = (const float*)d_in[9];
    const float* g_bn     = (const float*)d_in[10];
    const float* b_bn     = (const float*)d_in[11];
    const float* W_m2     = (const float*)d_in[12];
    const float* b_m2     = (const float*)d_in[13];
    const float* scale    = (const float*)d_in[14];
    const float* g_n      = (const float*)d_in[15];
    const float* b_n      = (const float*)d_in[16];
    const int* erow = eidx;
    const int* ecol = eidx + E_EDGES;
    float* xout  = (float*)d_out;
    float* e_out = (float*)d_out + (size_t)N_NODES * DD;

    cudaFuncSetAttribute((const void*)node_pre_kernel,
                         cudaFuncAttributeMaxDynamicSharedMemorySize, SM_TOTAL_TC);
    cudaFuncSetAttribute((const void*)edge_mlp_tc,
                         cudaFuncAttributeMaxDynamicSharedMemorySize, SM_TOTAL_TC);
    cudaFuncSetAttribute((const void*)mlp1_tc,
                         cudaFuncAttributeMaxDynamicSharedMemorySize, SM_TOTAL_TC);
    cudaFuncSetAttribute((const void*)mlp2_tc,
                         cudaFuncAttributeMaxDynamicSharedMemorySize, SM_TOTAL_TC);

    prep_kernel<<<(384 * 128 + 128 * 256 + 256 * 128 + 255) / 256, 256>>>(W_e, W_m1, W_m2);
    dim3 gn2((N_NODES + 127) / 128, 2);
    node_pre_kernel<<<gn2, 256, SM_TOTAL_TC>>>(x);
    edge_mlp_tc<<<(E_EDGES + 127) / 128, 256, SM_TOTAL_TC>>>(
        x, edge_attr, erow, ecol, b_e, g_e, be_e, t, e_out);
    mlp1_tc<<<gn2, 256, SM_TOTAL_TC>>>(x, b_m1);
    mlp2_tc<<<(N_NODES + 127) / 128, 256, SM_TOTAL_TC>>>(
        x, b_m2, scale, g_n, b_n, g_bn, b_bn, xout);
}